// round 11
// baseline (speedup 1.0000x reference)
#include <cuda_runtime.h>
#include <cstdint>

// ConditionalCNF via warp-level mma.sync (m16n8k8, tf32).
// R11: kernel is MUFU-bound (tanh.approx rt=16 exactly matches R10's 517
// cyc/warp-eval). Epilogue tanh -> ex2 (rt=8) + packed f32x2 Newton recip
// (magic-seed, 2 iters, err<=7e-6). Bias via MMA c-operand init (no FADDs,
// no acc zeroing). dv quad-reduction deferred past all 20 steps. Scalar
// layer-1. 16 samples/warp.

using u32 = unsigned int;
using ull = unsigned long long;

static constexpr int NSTEPS = 20;
static constexpr int BLK = 128;

__device__ __forceinline__ float tanh_approx(float x) {
    float y; asm("tanh.approx.f32 %0, %1;" : "=f"(y) : "f"(x)); return y;
}
__device__ __forceinline__ float ex2f(float x) {
    float y; asm("ex2.approx.f32 %0, %1;" : "=f"(y) : "f"(x)); return y;
}
__device__ __forceinline__ ull pack2(float lo, float hi) {
    ull r; asm("mov.b64 %0, {%1, %2};" : "=l"(r) : "f"(lo), "f"(hi)); return r;
}
__device__ __forceinline__ void unpack2(ull v, float& lo, float& hi) {
    asm("mov.b64 {%0, %1}, %2;" : "=f"(lo), "=f"(hi) : "l"(v));
}
__device__ __forceinline__ ull fma2o(ull a, ull b, ull c) {
    ull d; asm("fma.rn.f32x2 %0, %1, %2, %3;" : "=l"(d) : "l"(a), "l"(b), "l"(c));
    return d;
}
__device__ __forceinline__ ull mul2(ull a, ull b) {
    ull d; asm("mul.rn.f32x2 %0, %1, %2;" : "=l"(d) : "l"(a), "l"(b));
    return d;
}
__device__ __forceinline__ ull add2(ull a, ull b) {
    ull d; asm("add.rn.f32x2 %0, %1, %2;" : "=l"(d) : "l"(a), "l"(b));
    return d;
}
__device__ __forceinline__ u32 tf32_rna(float x) {
    u32 r; asm("cvt.rna.tf32.f32 %0, %1;" : "=r"(r) : "f"(x)); return r;
}
__device__ __forceinline__ void mma_acc(float& c0, float& c1, float& c2, float& c3,
                                        u32 a0, u32 a1, u32 a2, u32 a3,
                                        u32 b0, u32 b1) {
    asm volatile("mma.sync.aligned.m16n8k8.row.col.f32.tf32.tf32.f32 "
                 "{%0,%1,%2,%3}, {%4,%5,%6,%7}, {%8,%9}, {%0,%1,%2,%3};"
                 : "+f"(c0), "+f"(c1), "+f"(c2), "+f"(c3)
                 : "r"(a0), "r"(a1), "r"(a2), "r"(a3), "r"(b0), "r"(b1));
}
// init form: c = {cl, ch, cl, ch} (bias broadcast / zero) — no pre-zeroing movs
__device__ __forceinline__ void mma_init(float& d0, float& d1, float& d2, float& d3,
                                         u32 a0, u32 a1, u32 a2, u32 a3,
                                         u32 b0, u32 b1, float cl, float ch) {
    asm volatile("mma.sync.aligned.m16n8k8.row.col.f32.tf32.tf32.f32 "
                 "{%0,%1,%2,%3}, {%4,%5,%6,%7}, {%8,%9}, {%10,%11,%10,%11};"
                 : "=f"(d0), "=f"(d1), "=f"(d2), "=f"(d3)
                 : "r"(a0), "r"(a1), "r"(a2), "r"(a3), "r"(b0), "r"(b1),
                   "f"(cl), "f"(ch));
}

__global__ void __launch_bounds__(BLK, 5)
cnf_kernel(const float* __restrict__ T,
           const float* __restrict__ cond,
           const float* __restrict__ gW1,
           const float* __restrict__ gb1,
           const float* __restrict__ gW2,
           const float* __restrict__ gb2,
           const float* __restrict__ gW3,
           const float* __restrict__ gb3,
           float* __restrict__ out,
           int B)
{
    __shared__ float2 spre1[8 * BLK];  // layer1 preact pairs [slot][tid] (8 KB)
    __shared__ uint2  sB   [16 * 32];  // W2 tf32 B-frags [tile][lane]    (4 KB)
    __shared__ float2 sw10 [16];       // {w10[k0], w10[k1]} per (kt,c4)
    __shared__ float2 snw10[16];       // negated
    __shared__ float2 sb2  [16];       // {b2[n0], b2[n0+1]} per (nt,c4)
    __shared__ ull    sw3  [16];       // packed {w3[n0], w3[n0+1]}

    const int tid = threadIdx.x;
    const int ln  = tid & 31;
    const int wid = tid >> 5;
    const int q   = ln >> 2;
    const int c4  = ln & 3;

    // ---- one-time smem init ----
    for (int e = tid; e < 16 * 32; e += BLK) {
        int t = e >> 5, l = e & 31;
        int kt = t >> 2, nt = t & 3;
        int n  = (l >> 2) + 8 * nt;
        int k0 = (l & 3) + 8 * kt;
        sB[e] = make_uint2(tf32_rna(gW2[n * 32 + k0]),
                           tf32_rna(gW2[n * 32 + k0 + 4]));
    }
    if (tid < 16) {
        int kt = tid >> 2, cc = tid & 3;
        float w0 = gW1[(cc + 8 * kt) * 9];
        float w1 = gW1[(cc + 4 + 8 * kt) * 9];
        sw10[tid]  = make_float2(w0, w1);
        snw10[tid] = make_float2(-w0, -w1);
        int nt = tid >> 2;
        int n0 = 2 * cc + 8 * nt;
        sb2[tid] = make_float2(gb2[n0], gb2[n0 + 1]);
        sw3[tid] = pack2(gW3[n0], gW3[n0 + 1]);
    }

    // ---- per-thread setup: RK state + pre1 into smem ----
    const int gwbase = blockIdx.x * 64 + wid * 16;   // 16 samples per warp
    float z[2], logp[2];
#pragma unroll
    for (int rs = 0; rs < 2; rs++) {
        int s = gwbase + q + 8 * rs;
        z[rs] = __ldg(T + s);
        logp[rs] = 0.0f;
        const float4* cp = reinterpret_cast<const float4*>(cond) + s * 2;
        float4 ca = __ldg(cp), cb = __ldg(cp + 1);
        float cc[8] = {ca.x, ca.y, ca.z, ca.w, cb.x, cb.y, cb.z, cb.w};
#pragma unroll
        for (int kt = 0; kt < 4; kt++) {
            int k0 = c4 + 8 * kt, k1 = k0 + 4;
            float p0 = __ldg(gb1 + k0), p1 = __ldg(gb1 + k1);
#pragma unroll
            for (int c = 0; c < 8; c++) {
                p0 = fmaf(cc[c], __ldg(gW1 + k0 * 9 + 1 + c), p0);
                p1 = fmaf(cc[c], __ldg(gW1 + k1 * 9 + 1 + c), p1);
            }
            spre1[(rs * 4 + kt) * BLK + tid] = make_float2(p0, p1);
        }
    }
    const float b3v = __ldg(gb3);
    __syncthreads();

    const float dt  = 1.0f / (float)NSTEPS;
    const float dt6 = dt / 6.0f;
    const float KN  = -2.8853900817779268f;   // -2*log2(e)

    // packed f32x2 constants (persist in regs)
    const ull ONE2  = 0x3F8000003F800000ull;
    const ull NONE2 = 0xBF800000BF800000ull;
    const ull TWO2  = 0x4000000040000000ull;
    const ull NTWO2 = 0xC0000000C0000000ull;
    const ull MAGIC = 0x7EF311C37EF311C3ull;

#pragma unroll 1
    for (int step = 0; step < NSTEPS; step++) {
        float zs[2], az[2], ad2[2];
#pragma unroll
        for (int rs = 0; rs < 2; rs++) { zs[rs] = z[rs]; az[rs] = 0.0f; ad2[rs] = 0.0f; }

#pragma unroll 1
        for (int st = 0; st < 4; st++) {
            float accS[16], accT[16];

            // ---- fused scalar layer1 + dual matvec over kt ----
#pragma unroll
            for (int kt = 0; kt < 4; kt++) {
                float2 wv  = sw10 [kt * 4 + c4];
                float2 nwv = snw10[kt * 4 + c4];
                u32 ah[2][2], adf[2][2];
#pragma unroll
                for (int rs = 0; rs < 2; rs++) {
                    float2 pr = spre1[(rs * 4 + kt) * BLK + tid];
                    float x0 = fmaf(zs[rs], wv.x, pr.x);
                    float x1 = fmaf(zs[rs], wv.y, pr.y);
                    float h0 = tanh_approx(x0);
                    float h1 = tanh_approx(x1);
                    float g0 = fmaf(h0 * h0, nwv.x, wv.x);   // (1-h^2)*w10
                    float g1 = fmaf(h1 * h1, nwv.y, wv.y);
                    ah[rs][0]  = __float_as_uint(h0);
                    ah[rs][1]  = __float_as_uint(h1);
                    adf[rs][0] = __float_as_uint(g0);
                    adf[rs][1] = __float_as_uint(g1);
                }
#pragma unroll
                for (int nt = 0; nt < 4; nt++) {
                    uint2 bb = sB[(kt * 4 + nt) * 32 + ln];
                    int ba = nt * 4;
                    if (kt == 0) {
                        float2 bv = sb2[nt * 4 + c4];
                        mma_init(accS[ba], accS[ba+1], accS[ba+2], accS[ba+3],
                                 ah[0][0], ah[1][0], ah[0][1], ah[1][1],
                                 bb.x, bb.y, bv.x, bv.y);
                        mma_init(accT[ba], accT[ba+1], accT[ba+2], accT[ba+3],
                                 adf[0][0], adf[1][0], adf[0][1], adf[1][1],
                                 bb.x, bb.y, 0.0f, 0.0f);
                    } else {
                        mma_acc(accS[ba], accS[ba+1], accS[ba+2], accS[ba+3],
                                ah[0][0], ah[1][0], ah[0][1], ah[1][1],
                                bb.x, bb.y);
                        mma_acc(accT[ba], accT[ba+1], accT[ba+2], accT[ba+3],
                                adf[0][0], adf[1][0], adf[0][1], adf[1][1],
                                bb.x, bb.y);
                    }
                }
            }

            // ---- epilogue: tanh via ex2 + packed Newton recip ----
            // tanh(s) = sgn(s)*(1-t)/(1+t), t = ex2(KN*|s|)
            // g = 1-h^2 = 4*t*R^2, R = 1/(1+t)  (x4 folded into final logp)
            ull dzp[2] = {0ull, 0ull};
            ull dvp[2] = {0ull, 0ull};
#pragma unroll
            for (int nt = 0; nt < 4; nt++) {
                ull w3p = sw3[nt * 4 + c4];
                int ba = nt * 4;
#pragma unroll
                for (int rs = 0; rs < 2; rs++) {
                    int pb = ba + 2 * rs;
                    float s0 = accS[pb], s1 = accS[pb + 1];
                    float t0 = ex2f(KN * fabsf(s0));
                    float t1 = ex2f(KN * fabsf(s1));
                    ull tp  = pack2(t0, t1);
                    ull w   = add2(tp, ONE2);          // 1+t in [1,2]
                    ull r   = MAGIC - w;                // recip seed (bit trick)
                    ull q1  = fma2o(w, r, NTWO2);       // w*r - 2
                    ull r1n = mul2(r, q1);              // -r1
                    ull q2  = fma2o(w, r1n, TWO2);      // 2 - w*r1
                    ull r2n = mul2(r1n, q2);            // -R
                    ull num = add2(tp, NONE2);          // t-1
                    ull habs = mul2(num, r2n);          // (1-t)*R >= 0
                    ull sp  = pack2(s0, s1);
                    ull hs  = habs | (sp & 0x8000000080000000ull);
                    dzp[rs] = fma2o(w3p, hs, dzp[rs]);
                    ull rr  = mul2(r2n, r2n);           // R^2
                    ull g4  = mul2(tp, rr);             // t*R^2 = g/4
                    ull ap  = pack2(accT[pb], accT[pb + 1]);
                    ull u   = mul2(g4, ap);
                    dvp[rs] = fma2o(u, w3p, dvp[rs]);
                }
            }

            // ---- reduction (dz only; dv deferred) + RK accumulate ----
            const float coef = (st == 1 || st == 2) ? 2.0f : 1.0f;
            const float a = (st == 2) ? dt : (0.5f * dt);
#pragma unroll
            for (int rs = 0; rs < 2; rs++) {
                float dlo, dhi;
                unpack2(dzp[rs], dlo, dhi);
                float dz = dlo + dhi;
                dz += __shfl_xor_sync(0xffffffffu, dz, 1);
                dz += __shfl_xor_sync(0xffffffffu, dz, 2);
                float vlo, vhi;
                unpack2(dvp[rs], vlo, vhi);
                ad2[rs] = fmaf(coef, vlo + vhi, ad2[rs]);   // lane-partial
                float kz = dz + b3v;
                az[rs] = fmaf(coef, kz, az[rs]);
                zs[rs] = fmaf(a, kz, z[rs]);
            }
        }

#pragma unroll
        for (int rs = 0; rs < 2; rs++) {
            z[rs]    = fmaf(dt6, az[rs],  z[rs]);
            logp[rs] = fmaf(dt6, ad2[rs], logp[rs]);   // still /4, lane-partial
        }
    }

    // final: reduce logp over the quad, restore the x4 fold
#pragma unroll
    for (int rs = 0; rs < 2; rs++) {
        float lp = logp[rs];
        lp += __shfl_xor_sync(0xffffffffu, lp, 1);
        lp += __shfl_xor_sync(0xffffffffu, lp, 2);
        logp[rs] = 4.0f * lp;
    }

    if (c4 == 0) {
#pragma unroll
        for (int rs = 0; rs < 2; rs++) {
            int s = gwbase + q + 8 * rs;
            out[s]     = z[rs];
            out[B + s] = logp[rs];
        }
    }
}

extern "C" void kernel_launch(void* const* d_in, const int* in_sizes, int n_in,
                              void* d_out, int out_size) {
    const float* T    = (const float*)d_in[0];
    const float* cond = (const float*)d_in[1];
    const float* W1   = (const float*)d_in[2];
    const float* b1   = (const float*)d_in[3];
    const float* W2   = (const float*)d_in[4];
    const float* b2   = (const float*)d_in[5];
    const float* W3   = (const float*)d_in[6];
    const float* b3   = (const float*)d_in[7];
    float* out = (float*)d_out;

    const int B = in_sizes[0];
    const int blocks = (B + 63) / 64;   // 64 samples per CTA (16 per warp)
    cnf_kernel<<<blocks, BLK>>>(T, cond, W1, b1, W2, b2, W3, b3, out, B);
}

// round 12
// speedup vs baseline: 1.7226x; 1.7226x over previous
#include <cuda_runtime.h>
#include <cstdint>

// ConditionalCNF via warp-level mma.sync.
// R12: kernel proven MUFU-bound (R9 = 1051 cyc/warp-eval = 64 tanh x rt16).
// Layer-1 moves to tanh.approx.f16x2 (2 values per MUFU op) + f16 MMA
// m16n8k16 (f32 accum). f16 mantissa = tf32 mantissa (10 bits), so this is
// precision-parity with the R9 tf32 path. Epilogue keeps tanh.approx.f32.
// 32 samples/warp (R9 config, best measured).
//
//   lane: q = lane>>2, c4 = lane&3
//   sample rows per thread: {q+8rs, rs=0..3}
//   layer-1 k-units per thread: u0 = 16kt+8e+2c4, u0+1  (kt,e in {0,1})
//   D cols per thread: {2c4, 2c4+1} + 8nt

using u32 = unsigned int;
using ull = unsigned long long;

static constexpr int NSTEPS = 20;
static constexpr int BLK = 128;

__device__ __forceinline__ float tanh_approx(float x) {
    float y; asm("tanh.approx.f32 %0, %1;" : "=f"(y) : "f"(x)); return y;
}
__device__ __forceinline__ u32 cvt_f16x2(float hi, float lo) {
    u32 d; asm("cvt.rn.f16x2.f32 %0, %1, %2;" : "=r"(d) : "f"(hi), "f"(lo));
    return d;
}
__device__ __forceinline__ u32 tanh_h2(u32 x) {
    u32 d; asm("tanh.approx.f16x2 %0, %1;" : "=r"(d) : "r"(x)); return d;
}
__device__ __forceinline__ u32 hmul2o(u32 a, u32 b) {
    u32 d; asm("mul.rn.f16x2 %0, %1, %2;" : "=r"(d) : "r"(a), "r"(b));
    return d;
}
__device__ __forceinline__ u32 hfma2o(u32 a, u32 b, u32 c) {
    u32 d; asm("fma.rn.f16x2 %0, %1, %2, %3;" : "=r"(d) : "r"(a), "r"(b), "r"(c));
    return d;
}
// f16 MMA m16n8k16, f32 accumulate
__device__ __forceinline__ void mma_f16_acc(float& c0, float& c1, float& c2, float& c3,
                                            u32 a0, u32 a1, u32 a2, u32 a3,
                                            u32 b0, u32 b1) {
    asm volatile("mma.sync.aligned.m16n8k16.row.col.f32.f16.f16.f32 "
                 "{%0,%1,%2,%3}, {%4,%5,%6,%7}, {%8,%9}, {%0,%1,%2,%3};"
                 : "+f"(c0), "+f"(c1), "+f"(c2), "+f"(c3)
                 : "r"(a0), "r"(a1), "r"(a2), "r"(a3), "r"(b0), "r"(b1));
}
// init form: c = {cl, ch, cl, ch} (bias broadcast / zero) — no pre-zeroing movs
__device__ __forceinline__ void mma_f16_init(float& d0, float& d1, float& d2, float& d3,
                                             u32 a0, u32 a1, u32 a2, u32 a3,
                                             u32 b0, u32 b1, float cl, float ch) {
    asm volatile("mma.sync.aligned.m16n8k16.row.col.f32.f16.f16.f32 "
                 "{%0,%1,%2,%3}, {%4,%5,%6,%7}, {%8,%9}, {%10,%11,%10,%11};"
                 : "=f"(d0), "=f"(d1), "=f"(d2), "=f"(d3)
                 : "r"(a0), "r"(a1), "r"(a2), "r"(a3), "r"(b0), "r"(b1),
                   "f"(cl), "f"(ch));
}

__global__ void __launch_bounds__(BLK, 4)
cnf_kernel(const float* __restrict__ T,
           const float* __restrict__ cond,
           const float* __restrict__ gW1,
           const float* __restrict__ gb1,
           const float* __restrict__ gW2,
           const float* __restrict__ gb2,
           const float* __restrict__ gW3,
           const float* __restrict__ gb3,
           float* __restrict__ out,
           int B)
{
    __shared__ float2 spre1[16 * BLK];  // layer1 preact pairs [slot][tid] (16 KB)
    __shared__ uint2  sB   [8 * 32];    // W2 f16x2 B-frags [tile][lane]    (2 KB)
    __shared__ float2 swf  [16];        // w10 f32 pairs   [kp*4+c4]
    __shared__ u32    sw16 [16];        // w10 f16x2
    __shared__ u32    snw16[16];        // -w10 f16x2
    __shared__ float2 sb2  [16];        // {b2[n0], b2[n0+1]} per (nt,c4)
    __shared__ float2 sw3  [16];        // {w3[n0], w3[n0+1]}

    const int tid = threadIdx.x;
    const int ln  = tid & 31;
    const int wid = tid >> 5;
    const int q   = ln >> 2;
    const int c4  = ln & 3;

    // ---- one-time smem init ----
    // B f16 frags for m16n8k16: tile t = kt*4+nt (kt in {0,1}).
    // per lane l: n = (l>>2)+8nt; b0 = {W2[n,k0], W2[n,k0+1]} (lo=even k),
    // b1 = {W2[n,k0+8], W2[n,k0+9]}, k0 = 16kt + 2*(l&3).
    for (int e = tid; e < 8 * 32; e += BLK) {
        int t = e >> 5, l = e & 31;
        int kt = t >> 2, nt = t & 3;
        int n  = (l >> 2) + 8 * nt;
        int k0 = 16 * kt + 2 * (l & 3);
        const float* r = gW2 + n * 32 + k0;
        sB[e] = make_uint2(cvt_f16x2(r[1], r[0]), cvt_f16x2(r[9], r[8]));
    }
    if (tid < 16) {
        int kp = tid >> 2, cc = tid & 3;     // kp = 2*kt + e
        int kt = kp >> 1, ee = kp & 1;
        int u0 = 16 * kt + 8 * ee + 2 * cc;
        float w0 = gW1[u0 * 9], w1 = gW1[(u0 + 1) * 9];
        swf[tid]   = make_float2(w0, w1);
        sw16[tid]  = cvt_f16x2(w1, w0);
        snw16[tid] = cvt_f16x2(-w1, -w0);
        int nt = tid >> 2;
        int n0 = 2 * cc + 8 * nt;
        sb2[tid] = make_float2(gb2[n0], gb2[n0 + 1]);
        sw3[tid] = make_float2(gW3[n0], gW3[n0 + 1]);
    }

    // ---- per-thread setup: RK state + pre1 into smem ----
    const int gwbase = blockIdx.x * BLK + wid * 32;   // 32 samples per warp
    float z[4], logp[4];
#pragma unroll
    for (int rs = 0; rs < 4; rs++) {
        int s = gwbase + q + 8 * rs;
        z[rs] = __ldg(T + s);
        logp[rs] = 0.0f;
        const float4* cp = reinterpret_cast<const float4*>(cond) + s * 2;
        float4 ca = __ldg(cp), cb = __ldg(cp + 1);
        float cc[8] = {ca.x, ca.y, ca.z, ca.w, cb.x, cb.y, cb.z, cb.w};
#pragma unroll
        for (int kp = 0; kp < 4; kp++) {
            int kt = kp >> 1, ee = kp & 1;
            int u0 = 16 * kt + 8 * ee + 2 * c4;
            int u1 = u0 + 1;
            float p0 = __ldg(gb1 + u0), p1 = __ldg(gb1 + u1);
#pragma unroll
            for (int c = 0; c < 8; c++) {
                p0 = fmaf(cc[c], __ldg(gW1 + u0 * 9 + 1 + c), p0);
                p1 = fmaf(cc[c], __ldg(gW1 + u1 * 9 + 1 + c), p1);
            }
            spre1[(rs * 4 + kp) * BLK + tid] = make_float2(p0, p1);
        }
    }
    const float b3v = __ldg(gb3);
    __syncthreads();

    const float dt  = 1.0f / (float)NSTEPS;
    const float dt6 = dt / 6.0f;

#pragma unroll 1
    for (int step = 0; step < NSTEPS; step++) {
        float zs[4], az[4], ad4[4];
#pragma unroll
        for (int rs = 0; rs < 4; rs++) { zs[rs] = z[rs]; az[rs] = 0.0f; ad4[rs] = 0.0f; }

#pragma unroll 1
        for (int st = 0; st < 4; st++) {
            float accS[32], accT[32];

            // ---- fused layer1 (f16x2 tanh) + dual f16 matvec over kt ----
#pragma unroll
            for (int kt = 0; kt < 2; kt++) {
                u32 hA[4][2], gA[4][2];   // [rs][e]
#pragma unroll
                for (int ee = 0; ee < 2; ee++) {
                    int kp = 2 * kt + ee;
                    int idx = kp * 4 + c4;
                    float2 wv = swf[idx];
                    u32 w16 = sw16[idx], nw16 = snw16[idx];
#pragma unroll
                    for (int rs = 0; rs < 4; rs++) {
                        float2 pr = spre1[(rs * 4 + kp) * BLK + tid];
                        float x0 = fmaf(zs[rs], wv.x, pr.x);
                        float x1 = fmaf(zs[rs], wv.y, pr.y);
                        u32 h = tanh_h2(cvt_f16x2(x1, x0));
                        u32 hh = hmul2o(h, h);
                        hA[rs][ee] = h;
                        gA[rs][ee] = hfma2o(hh, nw16, w16);  // (1-h^2)*w10
                    }
                }
#pragma unroll
                for (int nt = 0; nt < 4; nt++) {
                    uint2 bb = sB[(kt * 4 + nt) * 32 + ln];
#pragma unroll
                    for (int mt = 0; mt < 2; mt++) {
                        int ba = (mt * 4 + nt) * 4;
                        if (kt == 0) {
                            float2 bv = sb2[nt * 4 + c4];
                            mma_f16_init(accS[ba], accS[ba+1], accS[ba+2], accS[ba+3],
                                         hA[2*mt][0], hA[2*mt+1][0], hA[2*mt][1], hA[2*mt+1][1],
                                         bb.x, bb.y, bv.x, bv.y);
                            mma_f16_init(accT[ba], accT[ba+1], accT[ba+2], accT[ba+3],
                                         gA[2*mt][0], gA[2*mt+1][0], gA[2*mt][1], gA[2*mt+1][1],
                                         bb.x, bb.y, 0.0f, 0.0f);
                        } else {
                            mma_f16_acc(accS[ba], accS[ba+1], accS[ba+2], accS[ba+3],
                                        hA[2*mt][0], hA[2*mt+1][0], hA[2*mt][1], hA[2*mt+1][1],
                                        bb.x, bb.y);
                            mma_f16_acc(accT[ba], accT[ba+1], accT[ba+2], accT[ba+3],
                                        gA[2*mt][0], gA[2*mt+1][0], gA[2*mt][1], gA[2*mt+1][1],
                                        bb.x, bb.y);
                        }
                    }
                }
            }

            // ---- merged epilogue: dz, dv per cell (f32 tanh) ----
            float dzp[4] = {0.f, 0.f, 0.f, 0.f};
            float dvp[4] = {0.f, 0.f, 0.f, 0.f};
#pragma unroll
            for (int mt = 0; mt < 2; mt++)
#pragma unroll
                for (int nt = 0; nt < 4; nt++) {
                    float2 wv = sw3[nt * 4 + c4];
                    int ba = (mt * 4 + nt) * 4;
                    float h2, g;
                    h2 = tanh_approx(accS[ba + 0]);
                    dzp[2*mt]   = fmaf(wv.x, h2, dzp[2*mt]);
                    g = fmaf(-h2, h2, 1.0f) * wv.x;
                    dvp[2*mt]   = fmaf(g, accT[ba + 0], dvp[2*mt]);
                    h2 = tanh_approx(accS[ba + 1]);
                    dzp[2*mt]   = fmaf(wv.y, h2, dzp[2*mt]);
                    g = fmaf(-h2, h2, 1.0f) * wv.y;
                    dvp[2*mt]   = fmaf(g, accT[ba + 1], dvp[2*mt]);
                    h2 = tanh_approx(accS[ba + 2]);
                    dzp[2*mt+1] = fmaf(wv.x, h2, dzp[2*mt+1]);
                    g = fmaf(-h2, h2, 1.0f) * wv.x;
                    dvp[2*mt+1] = fmaf(g, accT[ba + 2], dvp[2*mt+1]);
                    h2 = tanh_approx(accS[ba + 3]);
                    dzp[2*mt+1] = fmaf(wv.y, h2, dzp[2*mt+1]);
                    g = fmaf(-h2, h2, 1.0f) * wv.y;
                    dvp[2*mt+1] = fmaf(g, accT[ba + 3], dvp[2*mt+1]);
                }

            // ---- quad reduction + RK accumulate ----
            const float coef = (st == 1 || st == 2) ? 2.0f : 1.0f;
            const float a = (st == 2) ? dt : (0.5f * dt);
#pragma unroll
            for (int rs = 0; rs < 4; rs++) {
                float dz = dzp[rs], dv = dvp[rs];
                dz += __shfl_xor_sync(0xffffffffu, dz, 1);
                dz += __shfl_xor_sync(0xffffffffu, dz, 2);
                dv += __shfl_xor_sync(0xffffffffu, dv, 1);
                dv += __shfl_xor_sync(0xffffffffu, dv, 2);
                float kz = dz + b3v;
                az[rs]  = fmaf(coef, kz, az[rs]);
                ad4[rs] = fmaf(coef, dv, ad4[rs]);
                zs[rs]  = fmaf(a, kz, z[rs]);
            }
        }

#pragma unroll
        for (int rs = 0; rs < 4; rs++) {
            z[rs]    = fmaf(dt6, az[rs],  z[rs]);
            logp[rs] = fmaf(dt6, ad4[rs], logp[rs]);
        }
    }

    if (c4 == 0) {
#pragma unroll
        for (int rs = 0; rs < 4; rs++) {
            int s = gwbase + q + 8 * rs;
            out[s]     = z[rs];
            out[B + s] = logp[rs];
        }
    }
}

extern "C" void kernel_launch(void* const* d_in, const int* in_sizes, int n_in,
                              void* d_out, int out_size) {
    const float* T    = (const float*)d_in[0];
    const float* cond = (const float*)d_in[1];
    const float* W1   = (const float*)d_in[2];
    const float* b1   = (const float*)d_in[3];
    const float* W2   = (const float*)d_in[4];
    const float* b2   = (const float*)d_in[5];
    const float* W3   = (const float*)d_in[6];
    const float* b3   = (const float*)d_in[7];
    float* out = (float*)d_out;

    const int B = in_sizes[0];
    const int blocks = (B + BLK - 1) / BLK;   // 128 samples per CTA (32 per warp)
    cnf_kernel<<<blocks, BLK>>>(T, cond, W1, b1, W2, b2, W3, b3, out, B);
}